// round 15
// baseline (speedup 1.0000x reference)
#include <cuda_runtime.h>
#include <cuda_fp16.h>
#include <math.h>
#include <stdint.h>

typedef __half h16;
#define MROWS 65536
#define CIN   180
#define CC2   360
#define KPAD  192            // conv K padded (mult of 16)
#define NDTOT 3932160

// ---------------- scratch (uint4-backed, 16B aligned) ------------------------
__device__ uint4 g_inh4[1572864], g_inl4[1572864];   // in   frag [65536][192] h16
__device__ uint4 g_w1h4[9216],    g_w1l4[9216];      // W1^T frag [384][192]
__device__ uint4 g_w2h4[6144],    g_w2l4[6144];      // W2^T frag [256][192]
__device__ uint4 g_qh4[491520],   g_ql4[491520];     // Q    frag [Nw][D]
__device__ uint4 g_vth4[524288],  g_vtl4[524288];    // V^T  frag [Dp][Nw]
__device__ uint4 g_ah4[2097152],  g_al4[2097152];    // attn frag [Nw][Nw]
__device__ uint4 g_ych4[1572864], g_ycl4[1572864];   // Ycat frag [65536][192]
__device__ float g_X1[(size_t)MROWS * CC2];
__device__ float g_Yw[NDTOT];
__device__ float g_part[4194304];
__device__ float g_psum[256 * CC2], g_psq[256 * CC2];
__device__ float g_scale[CC2], g_shift[CC2];

// ---------------- helpers ----------------------------------------------------
__device__ __forceinline__ void split2h(float x, h16& h, h16& l) {
    h = __float2half(x);
    l = __float2half(x - __half2float(h));
}

__device__ __forceinline__ void mma_f16(float* d, const unsigned* a,
                                        const unsigned* b) {
    asm volatile(
        "mma.sync.aligned.m16n8k16.row.col.f32.f16.f16.f32 "
        "{%0,%1,%2,%3}, {%4,%5,%6,%7}, {%8,%9}, {%0,%1,%2,%3};"
        : "+f"(d[0]), "+f"(d[1]), "+f"(d[2]), "+f"(d[3])
        : "r"(a[0]), "r"(a[1]), "r"(a[2]), "r"(a[3]), "r"(b[0]), "r"(b[1]));
}

// Fragment layout (half units): chunk = (row>>3)*K16 + (k>>4); 128 halves/chunk.
// lane = (row&7)*4 + tg owns halves {k=2tg, 2tg+1, 2tg+8, 2tg+9} as one uint2.
__device__ __forceinline__ size_t frag_off16(int row, int k, int K16) {
    int tg   = (k & 7) >> 1;
    int elem = (k & 1) | (((k >> 3) & 1) << 1);
    return ((size_t)((row >> 3) * K16 + (k >> 4)) << 7)
         + ((row & 7) << 4) + (tg << 2) + elem;
}

// ============ NT tensor GEMM (fp16 3-term): C = A[M,K]*B[N,K]^T (+bias) =====
// Term-major MMA order (dependent-MMA spacing 8) + double-buffered smem with
// one __syncthreads per k-chunk. 128x128 tile, BK=16, 16 warps x 32x32.
__global__ __launch_bounds__(512) void gemm_hc(
    const h16* __restrict__ Ah, const h16* __restrict__ Al,
    const h16* __restrict__ Bh, const h16* __restrict__ Bl,
    float* __restrict__ C, int M, int N, int K16, int Kc16,
    const float* __restrict__ bias)
{
    __shared__ __align__(16) h16 As_h[2][2048], As_l[2][2048];
    __shared__ __align__(16) h16 Bs_h[2][2048], Bs_l[2][2048];

    const int tid  = threadIdx.x;
    const int row0 = blockIdx.y * 128;
    const int col0 = blockIdx.x * 128;
    const int kb0  = blockIdx.z * Kc16;
    const int kb1  = kb0 + Kc16;
    if (gridDim.z > 1) C += (size_t)blockIdx.z * M * N;

    const int wid = tid >> 5, lane = tid & 31;
    const int wm3 = (wid & 3) * 4;
    const int wn3 = (wid >> 2) * 4;
    const int g   = lane >> 2, tg = lane & 3;

    float acc[2][4][4];
#pragma unroll
    for (int mt = 0; mt < 2; mt++)
#pragma unroll
        for (int nt = 0; nt < 4; nt++)
#pragma unroll
            for (int j = 0; j < 4; j++) acc[mt][nt][j] = 0.f;

    const int ch = tid >> 5, ll = tid & 31;
    const h16* pAh = Ah + ((size_t)((row0 >> 3) + ch) * K16) * 128 + ll * 4;
    const h16* pAl = Al + ((size_t)((row0 >> 3) + ch) * K16) * 128 + ll * 4;
    const h16* pBh = Bh + ((size_t)((col0 >> 3) + ch) * K16) * 128 + ll * 4;
    const h16* pBl = Bl + ((size_t)((col0 >> 3) + ch) * K16) * 128 + ll * 4;
    const int sidx = tid * 4;

    uint2 rah, ral, rbh, rbl;
#define LOADK(KB)                                                  \
    do {                                                           \
        size_t o = (size_t)(KB) * 128;                             \
        rah = *reinterpret_cast<const uint2*>(pAh + o);            \
        ral = *reinterpret_cast<const uint2*>(pAl + o);            \
        rbh = *reinterpret_cast<const uint2*>(pBh + o);            \
        rbl = *reinterpret_cast<const uint2*>(pBl + o);            \
    } while (0)
#define STORE(BUF)                                                  \
    do {                                                            \
        *reinterpret_cast<uint2*>(&As_h[BUF][sidx]) = rah;          \
        *reinterpret_cast<uint2*>(&As_l[BUF][sidx]) = ral;          \
        *reinterpret_cast<uint2*>(&Bs_h[BUF][sidx]) = rbh;          \
        *reinterpret_cast<uint2*>(&Bs_l[BUF][sidx]) = rbl;          \
    } while (0)

    LOADK(kb0);
    STORE(0);
    __syncthreads();

    for (int kb = kb0; kb < kb1; kb++) {
        const int cur = (kb - kb0) & 1;
        if (kb + 1 < kb1) LOADK(kb + 1);   // LDG issue; latency covered by MMAs

        uint2 a_h[4], a_l[4], b_h[4], b_l[4];
#pragma unroll
        for (int j = 0; j < 4; j++) {
            a_h[j] = *reinterpret_cast<const uint2*>(&As_h[cur][(wm3 + j) * 128 + lane * 4]);
            a_l[j] = *reinterpret_cast<const uint2*>(&As_l[cur][(wm3 + j) * 128 + lane * 4]);
            b_h[j] = *reinterpret_cast<const uint2*>(&Bs_h[cur][(wn3 + j) * 128 + lane * 4]);
            b_l[j] = *reinterpret_cast<const uint2*>(&Bs_l[cur][(wn3 + j) * 128 + lane * 4]);
        }

        // term-major: all 8 accumulators between dependent MMAs
#pragma unroll
        for (int nt = 0; nt < 4; nt++) {          // hi*hi
            unsigned bu[2] = { b_h[nt].x, b_h[nt].y };
#pragma unroll
            for (int mt = 0; mt < 2; mt++) {
                unsigned au[4] = { a_h[2 * mt].x, a_h[2 * mt + 1].x,
                                   a_h[2 * mt].y, a_h[2 * mt + 1].y };
                mma_f16(acc[mt][nt], au, bu);
            }
        }
#pragma unroll
        for (int nt = 0; nt < 4; nt++) {          // hi*lo
            unsigned bu[2] = { b_l[nt].x, b_l[nt].y };
#pragma unroll
            for (int mt = 0; mt < 2; mt++) {
                unsigned au[4] = { a_h[2 * mt].x, a_h[2 * mt + 1].x,
                                   a_h[2 * mt].y, a_h[2 * mt + 1].y };
                mma_f16(acc[mt][nt], au, bu);
            }
        }
#pragma unroll
        for (int nt = 0; nt < 4; nt++) {          // lo*hi
            unsigned bu[2] = { b_h[nt].x, b_h[nt].y };
#pragma unroll
            for (int mt = 0; mt < 2; mt++) {
                unsigned au[4] = { a_l[2 * mt].x, a_l[2 * mt + 1].x,
                                   a_l[2 * mt].y, a_l[2 * mt + 1].y };
                mma_f16(acc[mt][nt], au, bu);
            }
        }

        if (kb + 1 < kb1) STORE(cur ^ 1);
        __syncthreads();
    }
#undef LOADK
#undef STORE

    // epilogue
#pragma unroll
    for (int mt = 0; mt < 2; mt++) {
        int r0 = row0 + wm3 * 8 + mt * 16 + g;
        int r1 = r0 + 8;
#pragma unroll
        for (int nt = 0; nt < 4; nt++) {
            int c0 = col0 + wn3 * 8 + nt * 8 + tg * 2;
            if (c0 < N) {
                float b0 = bias ? bias[c0] : 0.f;
                float b1 = bias ? bias[c0 + 1] : 0.f;
                float2 o0 = make_float2(acc[mt][nt][0] + b0, acc[mt][nt][1] + b1);
                float2 o1 = make_float2(acc[mt][nt][2] + b0, acc[mt][nt][3] + b1);
                *reinterpret_cast<float2*>(&C[(size_t)r0 * N + c0]) = o0;
                *reinterpret_cast<float2*>(&C[(size_t)r1 * N + c0]) = o1;
            }
        }
    }
}

// ====================== split-K reduce =======================================
__global__ void reduce_k(const float* __restrict__ part, float* __restrict__ dst,
                         int z, size_t len)
{
    size_t i = (size_t)blockIdx.x * 256 + threadIdx.x;
    if (i >= len) return;
    float s = 0.f;
    for (int zz = 0; zz < z; zz++) s += part[(size_t)zz * len + i];
    dst[i] = s;
}

// ====================== producers (write fragment layout) ====================
__global__ void to_rows(const float* __restrict__ src, h16* __restrict__ h,
                        h16* __restrict__ l, int Ks, int total)
{
    int idx = blockIdx.x * 256 + threadIdx.x;
    if (idx >= total) return;
    int r = idx / KPAD, k = idx - r * KPAD;
    float v = (k < Ks) ? src[(size_t)r * Ks + k] : 0.f;
    size_t o = frag_off16(r, k, KPAD / 16);
    split2h(v, h[o], l[o]);
}

__global__ void wt_rows(const float* __restrict__ W, h16* __restrict__ h,
                        h16* __restrict__ l, int Ks, int Ns, int total)
{
    int idx = blockIdx.x * 256 + threadIdx.x;
    if (idx >= total) return;
    int n = idx / KPAD, k = idx - n * KPAD;
    float v = (n < Ns && k < Ks) ? W[(size_t)k * Ns + n] : 0.f;
    size_t o = frag_off16(n, k, KPAD / 16);
    split2h(v, h[o], l[o]);
}

__global__ void bn_partial(const float* __restrict__ X1,
                           float* __restrict__ psum, float* __restrict__ psq)
{
    int ch = threadIdx.x;
    if (ch >= CC2) return;
    int b = blockIdx.x;
    const float* base = X1 + (size_t)b * 256 * CC2 + ch;
    float s = 0.f, q = 0.f;
    for (int r = 0; r < 256; r++) { float v = base[(size_t)r * CC2]; s += v; q += v * v; }
    psum[b * CC2 + ch] = s;
    psq[b * CC2 + ch]  = q;
}

__global__ void bn_final(const float* __restrict__ psum, const float* __restrict__ psq,
                         const float* __restrict__ bns, const float* __restrict__ bnb,
                         float* __restrict__ scl, float* __restrict__ shf)
{
    int ch = threadIdx.x;
    if (ch >= CC2) return;
    float s = 0.f, q = 0.f;
    for (int b = 0; b < 256; b++) { s += psum[b * CC2 + ch]; q += psq[b * CC2 + ch]; }
    float mean = s * (1.f / MROWS);
    float var  = q * (1.f / MROWS) - mean * mean;
    float sc = bns[ch] / sqrtf(var + 1e-5f);
    scl[ch] = sc;
    shf[ch] = bnb[ch] - mean * sc;
}

__device__ __forceinline__ size_t src_off(int n, int d, int lws, int& cc) {
    int ws = 1 << lws, sh = ws >> 1, lh = 7 - lws;
    int t = d / 60; cc = d - t * 60;
    int dw = t & (ws - 1), dh = t >> lws;
    int b = n >> (2 * lh);
    int rem = n & ((1 << (2 * lh)) - 1);
    int hh = rem >> lh, ww = rem & ((1 << lh) - 1);
    int r = ((hh << lws) + dh + sh) & 127;
    int s = ((ww << lws) + dw + sh) & 127;
    return (((size_t)b << 14) + ((size_t)r << 7) + s) * CC2;
}

__global__ void gather_q(const float* __restrict__ X1,
                         const float* __restrict__ scl, const float* __restrict__ shf,
                         h16* __restrict__ Qh, h16* __restrict__ Ql,
                         int gbase, int lws, int D, int total)
{
    int idx = blockIdx.x * 256 + threadIdx.x;
    if (idx >= total) return;
    int n = idx / D, d = idx - n * D;
    int cc;
    size_t off = src_off(n, d, lws, cc);
    int ch = gbase + cc;
    float q = X1[off + ch] * scl[ch] + shf[ch];
    size_t o = frag_off16(n, d, D / 16);
    split2h(q, Qh[o], Ql[o]);
}

__global__ void gather_vt(const float* __restrict__ X1,
                          const float* __restrict__ scl, const float* __restrict__ shf,
                          h16* __restrict__ Vh, h16* __restrict__ Vl,
                          int gbase, int lws, int D, int Nw, int total)
{
    int idx = blockIdx.x * 256 + threadIdx.x;
    if (idx >= total) return;
    int d = idx / Nw, n = idx - d * Nw;
    float v = 0.f;
    if (d < D) {
        int cc;
        size_t off = src_off(n, d, lws, cc);
        int ch = gbase + 60 + cc;
        v = X1[off + ch] * scl[ch] + shf[ch];
    }
    size_t o = frag_off16(d, n, Nw / 16);
    split2h(v, Vh[o], Vl[o]);
}

__global__ void scatter_split(const float* __restrict__ Yw,
                              h16* __restrict__ Ych, h16* __restrict__ Ycl,
                              int g, int lws)
{
    int idx = blockIdx.x * 256 + threadIdx.x;
    if (idx >= MROWS * 60) return;
    int cc = idx % 60;
    int m  = idx / 60;
    int so = m & 127, ro = (m >> 7) & 127, b = m >> 14;
    const int ws = 1 << lws, sh = ws >> 1, lh = 7 - lws;
    int r = (ro - sh) & 127, s = (so - sh) & 127;
    int hh = r >> lws, dh = r & (ws - 1);
    int ww = s >> lws, dw = s & (ws - 1);
    int n = (((b << lh) + hh) << lh) + ww;
    int D = (ws * ws) * 60;
    int d = ((dh << lws) + dw) * 60 + cc;
    float y = Yw[(size_t)n * D + d];
    size_t o = frag_off16(m, g * 60 + cc, KPAD / 16);
    split2h(y, Ych[o], Ycl[o]);
}

__global__ __launch_bounds__(256) void softmax_rows(float* __restrict__ data,
                                                    h16* __restrict__ oh,
                                                    h16* __restrict__ ol, int N)
{
    __shared__ float sb[4096];
    __shared__ float red[40];
    const int tid = threadIdx.x;
    const int row = blockIdx.x;
    float* p = data + (size_t)row * N;
    const int K16 = N >> 4;

    float mx = -3.402823466e+38f;
    for (int i = tid; i < N; i += 256) { float v = p[i]; sb[i] = v; mx = fmaxf(mx, v); }
#pragma unroll
    for (int o = 16; o > 0; o >>= 1) mx = fmaxf(mx, __shfl_xor_sync(0xffffffffu, mx, o));
    if ((tid & 31) == 0) red[tid >> 5] = mx;
    __syncthreads();
    if (tid == 0) {
        float m2 = red[0];
        for (int i = 1; i < 8; i++) m2 = fmaxf(m2, red[i]);
        red[32] = m2;
    }
    __syncthreads();
    const float mAll = red[32];
    float sum = 0.f;
    for (int i = tid; i < N; i += 256) { float e = expf(sb[i] - mAll); sb[i] = e; sum += e; }
#pragma unroll
    for (int o = 16; o > 0; o >>= 1) sum += __shfl_xor_sync(0xffffffffu, sum, o);
    __syncthreads();
    if ((tid & 31) == 0) red[tid >> 5] = sum;
    __syncthreads();
    if (tid == 0) {
        float s2 = 0.f;
        for (int i = 0; i < 8; i++) s2 += red[i];
        red[33] = 1.f / s2;
    }
    __syncthreads();
    const float inv = red[33];
    for (int i = tid; i < N; i += 256) {
        float v = sb[i] * inv;
        p[i] = v;
        size_t o = frag_off16(row, i, K16);
        split2h(v, oh[o], ol[o]);
    }
}

// ====================== host orchestration ===================================
extern "C" void kernel_launch(void* const* d_in, const int* in_sizes, int n_in,
                              void* d_out, int out_size)
{
    const float* in  = (const float*)d_in[0];
    const float* w1  = (const float*)d_in[1];
    const float* b1  = (const float*)d_in[2];
    const float* bns = (const float*)d_in[3];
    const float* bnb = (const float*)d_in[4];
    const float* w2  = (const float*)d_in[5];
    const float* b2  = (const float*)d_in[6];
    float* out = (float*)d_out;

    void* p;
    h16 *inh, *inl, *w1h, *w1l, *w2h, *w2l, *Qh, *Ql, *Vth, *Vtl, *ah, *al, *Ych, *Ycl;
    float *X1, *Yw, *part, *psum, *psq, *scl, *shf;
    cudaGetSymbolAddress(&p, g_inh4); inh = (h16*)p;
    cudaGetSymbolAddress(&p, g_inl4); inl = (h16*)p;
    cudaGetSymbolAddress(&p, g_w1h4); w1h = (h16*)p;
    cudaGetSymbolAddress(&p, g_w1l4); w1l = (h16*)p;
    cudaGetSymbolAddress(&p, g_w2h4); w2h = (h16*)p;
    cudaGetSymbolAddress(&p, g_w2l4); w2l = (h16*)p;
    cudaGetSymbolAddress(&p, g_qh4);  Qh  = (h16*)p;
    cudaGetSymbolAddress(&p, g_ql4);  Ql  = (h16*)p;
    cudaGetSymbolAddress(&p, g_vth4); Vth = (h16*)p;
    cudaGetSymbolAddress(&p, g_vtl4); Vtl = (h16*)p;
    cudaGetSymbolAddress(&p, g_ah4);  ah  = (h16*)p;
    cudaGetSymbolAddress(&p, g_al4);  al  = (h16*)p;
    cudaGetSymbolAddress(&p, g_ych4); Ych = (h16*)p;
    cudaGetSymbolAddress(&p, g_ycl4); Ycl = (h16*)p;
    cudaGetSymbolAddress(&p, g_X1);   X1  = (float*)p;
    cudaGetSymbolAddress(&p, g_Yw);   Yw  = (float*)p;
    cudaGetSymbolAddress(&p, g_part); part = (float*)p;
    cudaGetSymbolAddress(&p, g_psum); psum = (float*)p;
    cudaGetSymbolAddress(&p, g_psq);  psq  = (float*)p;
    cudaGetSymbolAddress(&p, g_scale); scl = (float*)p;
    cudaGetSymbolAddress(&p, g_shift); shf = (float*)p;

    // 0) fp16 hi/lo splits in fragment layout
    to_rows<<<MROWS * KPAD / 256, 256>>>(in, inh, inl, CIN, MROWS * KPAD);
    wt_rows<<<(384 * KPAD + 255) / 256, 256>>>(w1, w1h, w1l, CIN, CC2, 384 * KPAD);
    wt_rows<<<(256 * KPAD + 255) / 256, 256>>>(w2, w2h, w2l, CIN, CIN, 256 * KPAD);

    // 1) conv1: X1 = in @ W1 + b1 (NT vs W1^T frag; K16 = 12)
    gemm_hc<<<dim3(3, 512, 1), 512>>>(inh, inl, w1h, w1l, X1,
                                      MROWS, CC2, 12, 12, b1);

    // 2) BatchNorm stats
    bn_partial<<<256, 384>>>(X1, psum, psq);
    bn_final<<<1, 384>>>(psum, psq, bns, bnb, scl, shf);

    float* attn[3] = { out + 11796480, out + 28573696, out + 29622272 };
    const int lwsv[3] = {2, 3, 4};
    const int dpadv[3] = {1024, 3840, 15360};

    for (int g = 0; g < 3; g++) {
        const int lws = lwsv[g];
        const int ws  = 1 << lws;
        const int Nw  = 4 * (128 / ws) * (128 / ws);   // 4096 / 1024 / 256
        const int D   = ws * ws * 60;                   // 960 / 3840 / 15360
        const int Dp  = dpadv[g];

        // 3) gathers (BN affine fused, fp16 hi/lo fragment layout)
        gather_q<<<NDTOT / 256, 256>>>(X1, scl, shf, Qh, Ql, g * 120, lws, D, NDTOT);
        gather_vt<<<(Dp * Nw + 255) / 256, 256>>>(X1, scl, shf, Vth, Vtl,
                                                  g * 120, lws, D, Nw, Dp * Nw);

        // 4) logits S = Q @ Q^T (K = D)
        if (g == 0) {
            gemm_hc<<<dim3(32, 32, 1), 512>>>(Qh, Ql, Qh, Ql, attn[0],
                                              4096, 4096, 60, 60, nullptr);
        } else if (g == 1) {
            gemm_hc<<<dim3(8, 8, 4), 512>>>(Qh, Ql, Qh, Ql, part,
                                            1024, 1024, 240, 60, nullptr);
            reduce_k<<<4096, 256>>>(part, attn[1], 4, (size_t)1024 * 1024);
        } else {
            gemm_hc<<<dim3(2, 2, 60), 512>>>(Qh, Ql, Qh, Ql, part,
                                             256, 256, 960, 16, nullptr);
            reduce_k<<<256, 256>>>(part, attn[2], 60, (size_t)256 * 256);
        }

        // 5) softmax in place (d_out) + fp16 split (fragment layout)
        softmax_rows<<<Nw, 256>>>(attn[g], ah, al, Nw);

        // 6) Yw = attn @ V (NT vs V^T frag; K = Nw)
        gemm_hc<<<dim3(Dp / 128, Nw / 128, 1), 512>>>(ah, al, Vth, Vtl, Yw,
                                                      Nw, D, Nw / 16, Nw / 16, nullptr);

        // 7) scatter back + split for conv2 (k 180..191 remain zero)
        scatter_split<<<MROWS * 60 / 256, 256>>>(Yw, Ych, Ycl, g, lws);
    }

    // 8) conv2: y = Ycat @ W2 + b2
    gemm_hc<<<dim3(2, 512, 1), 512>>>(Ych, Ycl, w2h, w2l, out,
                                      MROWS, CIN, 12, 12, b2);
}

// round 16
// speedup vs baseline: 1.2398x; 1.2398x over previous
#include <cuda_runtime.h>
#include <cuda_fp16.h>
#include <math.h>
#include <stdint.h>

typedef __half h16;
#define MROWS 65536
#define CIN   180
#define CC2   360
#define KPAD  192            // conv K padded (mult of 16)
#define NDTOT 3932160

// ---------------- scratch (uint4-backed, 16B aligned) ------------------------
__device__ uint4 g_inh4[1572864], g_inl4[1572864];   // in   frag [65536][192] h16
__device__ uint4 g_w1h4[9216],    g_w1l4[9216];      // W1^T frag [384][192]
__device__ uint4 g_w2h4[6144],    g_w2l4[6144];      // W2^T frag [256][192]
__device__ uint4 g_qh4[491520],   g_ql4[491520];     // Q    frag [Nw][D]
__device__ uint4 g_vth4[524288],  g_vtl4[524288];    // V^T  frag [Dp][Nw]
__device__ uint4 g_ah4[2097152],  g_al4[2097152];    // attn frag [Nw][Nw]
__device__ uint4 g_ych4[1572864], g_ycl4[1572864];   // Ycat frag [65536][192]
__device__ float g_X1[(size_t)MROWS * CC2];
__device__ float g_Yw[NDTOT];
__device__ float g_part[4194304];
__device__ float g_psum[256 * CC2], g_psq[256 * CC2];
__device__ float g_scale[CC2], g_shift[CC2];

// ---------------- helpers ----------------------------------------------------
__device__ __forceinline__ void split2h(float x, h16& h, h16& l) {
    h = __float2half(x);
    l = __float2half(x - __half2float(h));
}

__device__ __forceinline__ void mma_f16(float* d, const unsigned* a,
                                        const unsigned* b) {
    asm volatile(
        "mma.sync.aligned.m16n8k16.row.col.f32.f16.f16.f32 "
        "{%0,%1,%2,%3}, {%4,%5,%6,%7}, {%8,%9}, {%0,%1,%2,%3};"
        : "+f"(d[0]), "+f"(d[1]), "+f"(d[2]), "+f"(d[3])
        : "r"(a[0]), "r"(a[1]), "r"(a[2]), "r"(a[3]), "r"(b[0]), "r"(b[1]));
}

__device__ __forceinline__ void cp16(uint32_t s, const void* g) {
    asm volatile("cp.async.cg.shared.global [%0], [%1], 16;" :: "r"(s), "l"(g));
}
__device__ __forceinline__ void cp_commit() {
    asm volatile("cp.async.commit_group;" ::: "memory");
}
template <int NP> __device__ __forceinline__ void cp_wait() {
    asm volatile("cp.async.wait_group %0;" :: "n"(NP) : "memory");
}

// Fragment layout (half units): chunk = (row>>3)*K16 + (k>>4); 128 halves/chunk.
// lane = (row&7)*4 + tg owns halves {k=2tg, 2tg+1, 2tg+8, 2tg+9} as one uint2.
__device__ __forceinline__ size_t frag_off16(int row, int k, int K16) {
    int tg   = (k & 7) >> 1;
    int elem = (k & 1) | (((k >> 3) & 1) << 1);
    return ((size_t)((row >> 3) * K16 + (k >> 4)) << 7)
         + ((row & 7) << 4) + (tg << 2) + elem;
}

// ============ NT tensor GEMM (fp16 3-term): C = A[M,K]*B[N,K]^T (+bias) =====
// R14 MMA inner loop + cp.async 3-stage staging (16KB/stage, 48KB total).
// 128x128 tile, BK=16, 512 threads = 16 warps x 32x32 microtile.
__global__ __launch_bounds__(512) void gemm_hc(
    const h16* __restrict__ Ah, const h16* __restrict__ Al,
    const h16* __restrict__ Bh, const h16* __restrict__ Bl,
    float* __restrict__ C, int M, int N, int K16, int Kc16,
    const float* __restrict__ bias)
{
    extern __shared__ __align__(16) h16 smp[];   // 3 stages x 8192 halves

    const int tid  = threadIdx.x;
    const int row0 = blockIdx.y * 128;
    const int col0 = blockIdx.x * 128;
    const int kb0  = blockIdx.z * Kc16;
    const int kb1  = kb0 + Kc16;
    if (gridDim.z > 1) C += (size_t)blockIdx.z * M * N;

    const int wid = tid >> 5, lane = tid & 31;
    const int wm3 = (wid & 3) * 4;
    const int wn3 = (wid >> 2) * 4;
    const int g   = lane >> 2, tg = lane & 3;

    float acc[2][4][4];
#pragma unroll
    for (int mt = 0; mt < 2; mt++)
#pragma unroll
        for (int nt = 0; nt < 4; nt++)
#pragma unroll
            for (int j = 0; j < 4; j++) acc[mt][nt][j] = 0.f;

    // loader: thread -> array (tid>>7), two 16B segments (seg, seg+128)
    const int arr  = tid >> 7;               // 0=Ah 1=Al 2=Bh 3=Bl
    const int seg0 = tid & 127;              // 0..127 (seg1 = seg0+128)
    const int ch0  = seg0 >> 4;              // chunk 0..7  (second: +8)
    const int wo   = (seg0 & 15) * 8;        // within-chunk half offset
    const int rb   = ((arr < 2 ? row0 : col0) >> 3);
    const h16* abase = (arr == 0) ? Ah : (arr == 1) ? Al : (arr == 2) ? Bh : Bl;
    const h16* gp0 = abase + ((size_t)(rb + ch0)     * K16) * 128 + wo;
    const h16* gp1 = abase + ((size_t)(rb + ch0 + 8) * K16) * 128 + wo;
    const uint32_t sb = (uint32_t)__cvta_generic_to_shared(smp);
    const uint32_t sd0 = sb + (uint32_t)(arr * 4096 + seg0 * 16);

#define ISSUE(KB, ST) do {                                            \
        size_t o = (size_t)(KB) * 128;                                \
        uint32_t d = sd0 + (uint32_t)(ST) * 16384u;                   \
        cp16(d,         gp0 + o);                                     \
        cp16(d + 2048u, gp1 + o);                                     \
        cp_commit();                                                  \
    } while (0)

    ISSUE(kb0, 0);
    if (kb0 + 1 < kb1) ISSUE(kb0 + 1, 1);

    for (int kb = kb0; kb < kb1; kb++) {
        if (kb + 1 < kb1) cp_wait<1>(); else cp_wait<0>();
        __syncthreads();
        if (kb + 2 < kb1) ISSUE(kb + 2, (kb - kb0 + 2) % 3);

        const int st = (kb - kb0) % 3;
        const h16* As_h = smp + st * 8192;
        const h16* As_l = As_h + 2048;
        const h16* Bs_h = As_h + 4096;
        const h16* Bs_l = As_h + 6144;

        uint2 a_h[4], a_l[4];
#pragma unroll
        for (int j = 0; j < 4; j++) {
            a_h[j] = *reinterpret_cast<const uint2*>(&As_h[(wm3 + j) * 128 + lane * 4]);
            a_l[j] = *reinterpret_cast<const uint2*>(&As_l[(wm3 + j) * 128 + lane * 4]);
        }
#pragma unroll
        for (int nt = 0; nt < 4; nt++) {
            uint2 bh = *reinterpret_cast<const uint2*>(&Bs_h[(wn3 + nt) * 128 + lane * 4]);
            uint2 bl = *reinterpret_cast<const uint2*>(&Bs_l[(wn3 + nt) * 128 + lane * 4]);
            unsigned bhu[2] = { bh.x, bh.y };
            unsigned blu[2] = { bl.x, bl.y };
#pragma unroll
            for (int mt = 0; mt < 2; mt++) {
                unsigned ahu[4] = { a_h[2 * mt].x, a_h[2 * mt + 1].x,
                                    a_h[2 * mt].y, a_h[2 * mt + 1].y };
                unsigned alu[4] = { a_l[2 * mt].x, a_l[2 * mt + 1].x,
                                    a_l[2 * mt].y, a_l[2 * mt + 1].y };
                mma_f16(acc[mt][nt], ahu, bhu);   // hi*hi
                mma_f16(acc[mt][nt], ahu, blu);   // hi*lo
                mma_f16(acc[mt][nt], alu, bhu);   // lo*hi
            }
        }
    }
#undef ISSUE

    // epilogue
#pragma unroll
    for (int mt = 0; mt < 2; mt++) {
        int r0 = row0 + wm3 * 8 + mt * 16 + g;
        int r1 = r0 + 8;
#pragma unroll
        for (int nt = 0; nt < 4; nt++) {
            int c0 = col0 + wn3 * 8 + nt * 8 + tg * 2;
            if (c0 < N) {
                float b0 = bias ? bias[c0] : 0.f;
                float b1 = bias ? bias[c0 + 1] : 0.f;
                float2 o0 = make_float2(acc[mt][nt][0] + b0, acc[mt][nt][1] + b1);
                float2 o1 = make_float2(acc[mt][nt][2] + b0, acc[mt][nt][3] + b1);
                *reinterpret_cast<float2*>(&C[(size_t)r0 * N + c0]) = o0;
                *reinterpret_cast<float2*>(&C[(size_t)r1 * N + c0]) = o1;
            }
        }
    }
}

#define GSM 49152

// ====================== split-K reduce =======================================
__global__ void reduce_k(const float* __restrict__ part, float* __restrict__ dst,
                         int z, size_t len)
{
    size_t i = (size_t)blockIdx.x * 256 + threadIdx.x;
    if (i >= len) return;
    float s = 0.f;
    for (int zz = 0; zz < z; zz++) s += part[(size_t)zz * len + i];
    dst[i] = s;
}

// ====================== producers (write fragment layout) ====================
__global__ void to_rows(const float* __restrict__ src, h16* __restrict__ h,
                        h16* __restrict__ l, int Ks, int total)
{
    int idx = blockIdx.x * 256 + threadIdx.x;
    if (idx >= total) return;
    int r = idx / KPAD, k = idx - r * KPAD;
    float v = (k < Ks) ? src[(size_t)r * Ks + k] : 0.f;
    size_t o = frag_off16(r, k, KPAD / 16);
    split2h(v, h[o], l[o]);
}

__global__ void wt_rows(const float* __restrict__ W, h16* __restrict__ h,
                        h16* __restrict__ l, int Ks, int Ns, int total)
{
    int idx = blockIdx.x * 256 + threadIdx.x;
    if (idx >= total) return;
    int n = idx / KPAD, k = idx - n * KPAD;
    float v = (n < Ns && k < Ks) ? W[(size_t)k * Ns + n] : 0.f;
    size_t o = frag_off16(n, k, KPAD / 16);
    split2h(v, h[o], l[o]);
}

__global__ void bn_partial(const float* __restrict__ X1,
                           float* __restrict__ psum, float* __restrict__ psq)
{
    int ch = threadIdx.x;
    if (ch >= CC2) return;
    int b = blockIdx.x;
    const float* base = X1 + (size_t)b * 256 * CC2 + ch;
    float s = 0.f, q = 0.f;
    for (int r = 0; r < 256; r++) { float v = base[(size_t)r * CC2]; s += v; q += v * v; }
    psum[b * CC2 + ch] = s;
    psq[b * CC2 + ch]  = q;
}

__global__ void bn_final(const float* __restrict__ psum, const float* __restrict__ psq,
                         const float* __restrict__ bns, const float* __restrict__ bnb,
                         float* __restrict__ scl, float* __restrict__ shf)
{
    int ch = threadIdx.x;
    if (ch >= CC2) return;
    float s = 0.f, q = 0.f;
    for (int b = 0; b < 256; b++) { s += psum[b * CC2 + ch]; q += psq[b * CC2 + ch]; }
    float mean = s * (1.f / MROWS);
    float var  = q * (1.f / MROWS) - mean * mean;
    float sc = bns[ch] / sqrtf(var + 1e-5f);
    scl[ch] = sc;
    shf[ch] = bnb[ch] - mean * sc;
}

__device__ __forceinline__ size_t src_off(int n, int d, int lws, int& cc) {
    int ws = 1 << lws, sh = ws >> 1, lh = 7 - lws;
    int t = d / 60; cc = d - t * 60;
    int dw = t & (ws - 1), dh = t >> lws;
    int b = n >> (2 * lh);
    int rem = n & ((1 << (2 * lh)) - 1);
    int hh = rem >> lh, ww = rem & ((1 << lh) - 1);
    int r = ((hh << lws) + dh + sh) & 127;
    int s = ((ww << lws) + dw + sh) & 127;
    return (((size_t)b << 14) + ((size_t)r << 7) + s) * CC2;
}

__global__ void gather_q(const float* __restrict__ X1,
                         const float* __restrict__ scl, const float* __restrict__ shf,
                         h16* __restrict__ Qh, h16* __restrict__ Ql,
                         int gbase, int lws, int D, int total)
{
    int idx = blockIdx.x * 256 + threadIdx.x;
    if (idx >= total) return;
    int n = idx / D, d = idx - n * D;
    int cc;
    size_t off = src_off(n, d, lws, cc);
    int ch = gbase + cc;
    float q = X1[off + ch] * scl[ch] + shf[ch];
    size_t o = frag_off16(n, d, D / 16);
    split2h(q, Qh[o], Ql[o]);
}

__global__ void gather_vt(const float* __restrict__ X1,
                          const float* __restrict__ scl, const float* __restrict__ shf,
                          h16* __restrict__ Vh, h16* __restrict__ Vl,
                          int gbase, int lws, int D, int Nw, int total)
{
    int idx = blockIdx.x * 256 + threadIdx.x;
    if (idx >= total) return;
    int d = idx / Nw, n = idx - d * Nw;
    float v = 0.f;
    if (d < D) {
        int cc;
        size_t off = src_off(n, d, lws, cc);
        int ch = gbase + 60 + cc;
        v = X1[off + ch] * scl[ch] + shf[ch];
    }
    size_t o = frag_off16(d, n, Nw / 16);
    split2h(v, Vh[o], Vl[o]);
}

__global__ void scatter_split(const float* __restrict__ Yw,
                              h16* __restrict__ Ych, h16* __restrict__ Ycl,
                              int g, int lws)
{
    int idx = blockIdx.x * 256 + threadIdx.x;
    if (idx >= MROWS * 60) return;
    int cc = idx % 60;
    int m  = idx / 60;
    int so = m & 127, ro = (m >> 7) & 127, b = m >> 14;
    const int ws = 1 << lws, sh = ws >> 1, lh = 7 - lws;
    int r = (ro - sh) & 127, s = (so - sh) & 127;
    int hh = r >> lws, dh = r & (ws - 1);
    int ww = s >> lws, dw = s & (ws - 1);
    int n = (((b << lh) + hh) << lh) + ww;
    int D = (ws * ws) * 60;
    int d = ((dh << lws) + dw) * 60 + cc;
    float y = Yw[(size_t)n * D + d];
    size_t o = frag_off16(m, g * 60 + cc, KPAD / 16);
    split2h(y, Ych[o], Ycl[o]);
}

__global__ __launch_bounds__(256) void softmax_rows(float* __restrict__ data,
                                                    h16* __restrict__ oh,
                                                    h16* __restrict__ ol, int N)
{
    __shared__ float sb[4096];
    __shared__ float red[40];
    const int tid = threadIdx.x;
    const int row = blockIdx.x;
    float* p = data + (size_t)row * N;
    const int K16 = N >> 4;

    float mx = -3.402823466e+38f;
    for (int i = tid; i < N; i += 256) { float v = p[i]; sb[i] = v; mx = fmaxf(mx, v); }
#pragma unroll
    for (int o = 16; o > 0; o >>= 1) mx = fmaxf(mx, __shfl_xor_sync(0xffffffffu, mx, o));
    if ((tid & 31) == 0) red[tid >> 5] = mx;
    __syncthreads();
    if (tid == 0) {
        float m2 = red[0];
        for (int i = 1; i < 8; i++) m2 = fmaxf(m2, red[i]);
        red[32] = m2;
    }
    __syncthreads();
    const float mAll = red[32];
    float sum = 0.f;
    for (int i = tid; i < N; i += 256) { float e = expf(sb[i] - mAll); sb[i] = e; sum += e; }
#pragma unroll
    for (int o = 16; o > 0; o >>= 1) sum += __shfl_xor_sync(0xffffffffu, sum, o);
    __syncthreads();
    if ((tid & 31) == 0) red[tid >> 5] = sum;
    __syncthreads();
    if (tid == 0) {
        float s2 = 0.f;
        for (int i = 0; i < 8; i++) s2 += red[i];
        red[33] = 1.f / s2;
    }
    __syncthreads();
    const float inv = red[33];
    for (int i = tid; i < N; i += 256) {
        float v = sb[i] * inv;
        p[i] = v;
        size_t o = frag_off16(row, i, K16);
        split2h(v, oh[o], ol[o]);
    }
}

// ====================== host orchestration ===================================
extern "C" void kernel_launch(void* const* d_in, const int* in_sizes, int n_in,
                              void* d_out, int out_size)
{
    const float* in  = (const float*)d_in[0];
    const float* w1  = (const float*)d_in[1];
    const float* b1  = (const float*)d_in[2];
    const float* bns = (const float*)d_in[3];
    const float* bnb = (const float*)d_in[4];
    const float* w2  = (const float*)d_in[5];
    const float* b2  = (const float*)d_in[6];
    float* out = (float*)d_out;

    cudaFuncSetAttribute(gemm_hc, cudaFuncAttributeMaxDynamicSharedMemorySize, GSM);

    void* p;
    h16 *inh, *inl, *w1h, *w1l, *w2h, *w2l, *Qh, *Ql, *Vth, *Vtl, *ah, *al, *Ych, *Ycl;
    float *X1, *Yw, *part, *psum, *psq, *scl, *shf;
    cudaGetSymbolAddress(&p, g_inh4); inh = (h16*)p;
    cudaGetSymbolAddress(&p, g_inl4); inl = (h16*)p;
    cudaGetSymbolAddress(&p, g_w1h4); w1h = (h16*)p;
    cudaGetSymbolAddress(&p, g_w1l4); w1l = (h16*)p;
    cudaGetSymbolAddress(&p, g_w2h4); w2h = (h16*)p;
    cudaGetSymbolAddress(&p, g_w2l4); w2l = (h16*)p;
    cudaGetSymbolAddress(&p, g_qh4);  Qh  = (h16*)p;
    cudaGetSymbolAddress(&p, g_ql4);  Ql  = (h16*)p;
    cudaGetSymbolAddress(&p, g_vth4); Vth = (h16*)p;
    cudaGetSymbolAddress(&p, g_vtl4); Vtl = (h16*)p;
    cudaGetSymbolAddress(&p, g_ah4);  ah  = (h16*)p;
    cudaGetSymbolAddress(&p, g_al4);  al  = (h16*)p;
    cudaGetSymbolAddress(&p, g_ych4); Ych = (h16*)p;
    cudaGetSymbolAddress(&p, g_ycl4); Ycl = (h16*)p;
    cudaGetSymbolAddress(&p, g_X1);   X1  = (float*)p;
    cudaGetSymbolAddress(&p, g_Yw);   Yw  = (float*)p;
    cudaGetSymbolAddress(&p, g_part); part = (float*)p;
    cudaGetSymbolAddress(&p, g_psum); psum = (float*)p;
    cudaGetSymbolAddress(&p, g_psq);  psq  = (float*)p;
    cudaGetSymbolAddress(&p, g_scale); scl = (float*)p;
    cudaGetSymbolAddress(&p, g_shift); shf = (float*)p;

    // 0) fp16 hi/lo splits in fragment layout
    to_rows<<<MROWS * KPAD / 256, 256>>>(in, inh, inl, CIN, MROWS * KPAD);
    wt_rows<<<(384 * KPAD + 255) / 256, 256>>>(w1, w1h, w1l, CIN, CC2, 384 * KPAD);
    wt_rows<<<(256 * KPAD + 255) / 256, 256>>>(w2, w2h, w2l, CIN, CIN, 256 * KPAD);

    // 1) conv1: X1 = in @ W1 + b1 (NT vs W1^T frag; K16 = 12)
    gemm_hc<<<dim3(3, 512, 1), 512, GSM>>>(inh, inl, w1h, w1l, X1,
                                           MROWS, CC2, 12, 12, b1);

    // 2) BatchNorm stats
    bn_partial<<<256, 384>>>(X1, psum, psq);
    bn_final<<<1, 384>>>(psum, psq, bns, bnb, scl, shf);

    float* attn[3] = { out + 11796480, out + 28573696, out + 29622272 };
    const int lwsv[3] = {2, 3, 4};
    const int dpadv[3] = {1024, 3840, 15360};

    for (int g = 0; g < 3; g++) {
        const int lws = lwsv[g];
        const int ws  = 1 << lws;
        const int Nw  = 4 * (128 / ws) * (128 / ws);   // 4096 / 1024 / 256
        const int D   = ws * ws * 60;                   // 960 / 3840 / 15360
        const int Dp  = dpadv[g];

        // 3) gathers (BN affine fused, fp16 hi/lo fragment layout)
        gather_q<<<NDTOT / 256, 256>>>(X1, scl, shf, Qh, Ql, g * 120, lws, D, NDTOT);
        gather_vt<<<(Dp * Nw + 255) / 256, 256>>>(X1, scl, shf, Vth, Vtl,
                                                  g * 120, lws, D, Nw, Dp * Nw);

        // 4) logits S = Q @ Q^T (K = D)
        if (g == 0) {
            gemm_hc<<<dim3(32, 32, 1), 512, GSM>>>(Qh, Ql, Qh, Ql, attn[0],
                                                   4096, 4096, 60, 60, nullptr);
        } else if (g == 1) {
            gemm_hc<<<dim3(8, 8, 4), 512, GSM>>>(Qh, Ql, Qh, Ql, part,
                                                 1024, 1024, 240, 60, nullptr);
            reduce_k<<<4096, 256>>>(part, attn[1], 4, (size_t)1024 * 1024);
        } else {
            gemm_hc<<<dim3(2, 2, 60), 512, GSM>>>(Qh, Ql, Qh, Ql, part,
                                                  256, 256, 960, 16, nullptr);
            reduce_k<<<256, 256>>>(part, attn[2], 60, (size_t)256 * 256);
        }

        // 5) softmax in place (d_out) + fp16 split (fragment layout)
        softmax_rows<<<Nw, 256>>>(attn[g], ah, al, Nw);

        // 6) Yw = attn @ V (NT vs V^T frag; K = Nw)
        gemm_hc<<<dim3(Dp / 128, Nw / 128, 1), 512, GSM>>>(ah, al, Vth, Vtl, Yw,
                                                           Nw, D, Nw / 16, Nw / 16, nullptr);

        // 7) scatter back + split for conv2 (k 180..191 remain zero)
        scatter_split<<<MROWS * 60 / 256, 256>>>(Yw, Ych, Ycl, g, lws);
    }

    // 8) conv2: y = Ycat @ W2 + b2
    gemm_hc<<<dim3(2, 512, 1), 512, GSM>>>(Ych, Ycl, w2h, w2l, out,
                                           MROWS, CIN, 12, 12, b2);
}